// round 7
// baseline (speedup 1.0000x reference)
#include <cuda_runtime.h>
#include <math.h>
#include <stdint.h>

#define BB 32
#define TT 512
#define EE 256
#define UU 512
#define U3 1536
#define NBLK 64          // blocks per direction in recurrence
#define RGRID (2*NBLK)   // total recurrence blocks
#define PADK 516         // padded k-stride for h rows (conflict-free LDS)
#define PK2  521         // float2 stride for U hi/lo (conflict-free LDS.64)
#define PSB  5           // psum batch stride (4 slots + pad)
#define PSC  164         // psum col stride (32*5 + pad, conflict-free epilogue)

// ---------------- device scratch (static; no runtime allocation) ------------
__device__ float    g_xproj[2][BB][TT][U3];   // x@W + b_in per direction
__device__ float    g_h[2][2][BB][UU];        // [dir][buf][b][u] double-buffered state
__device__ unsigned g_flag[2][TT][NBLK];      // per-step arrival flags (memset to 0)

// ---------------- packed f32x2 helpers (xproj kernel) -----------------------
__device__ __forceinline__ unsigned long long ffma2(unsigned long long a,
                                                    unsigned long long b,
                                                    unsigned long long c) {
    unsigned long long d;
    asm("fma.rn.f32x2 %0, %1, %2, %3;" : "=l"(d) : "l"(a), "l"(b), "l"(c));
    return d;
}
__device__ __forceinline__ unsigned long long dup2(float x) {
    unsigned long long d;
    asm("mov.b64 %0, {%1, %1};" : "=l"(d) : "f"(x));
    return d;
}
__device__ __forceinline__ float2 unpack2(unsigned long long v) {
    float2 r;
    asm("mov.b64 {%0, %1}, %2;" : "=f"(r.x), "=f"(r.y) : "l"(v));
    return r;
}

// ---------------- tf32 mma helper -------------------------------------------
__device__ __forceinline__ void mma_tf32(float& d0, float& d1, float& d2, float& d3,
                                         unsigned a0, unsigned a1, unsigned a2, unsigned a3,
                                         unsigned b0, unsigned b1) {
    asm volatile(
        "mma.sync.aligned.m16n8k8.row.col.f32.tf32.tf32.f32 "
        "{%0,%1,%2,%3}, {%4,%5,%6,%7}, {%8,%9}, {%0,%1,%2,%3};"
        : "+f"(d0), "+f"(d1), "+f"(d2), "+f"(d3)
        : "r"(a0), "r"(a1), "r"(a2), "r"(a3), "r"(b0), "r"(b1));
}
__device__ __forceinline__ unsigned tf32_hi_bits(float x) {
    return __float_as_uint(x) & 0xFFFFE000u;
}

// ---------------- Kernel A: x_proj = emb[tokens] @ W + b_in -----------------
#define BM 128
#define BN 64
#define BK 16

__global__ void __launch_bounds__(256) xproj_kernel(
    const int* __restrict__ tokens,
    const float* __restrict__ emb,
    const float* __restrict__ W_fw, const float* __restrict__ b_in_fw,
    const float* __restrict__ W_bw, const float* __restrict__ b_in_bw)
{
    __shared__ __align__(16) float As[BK][BM];
    __shared__ __align__(16) float Bs[BK][BN];
    __shared__ int toks[BM];

    const int d  = blockIdx.z;
    const float* __restrict__ Wp = d ? W_bw : W_fw;
    const float* __restrict__ bp = d ? b_in_bw : b_in_fw;
    const int n0 = blockIdx.x * BN;
    const int m0 = blockIdx.y * BM;
    const int tid = threadIdx.x;
    const int tx = tid & 15;
    const int ty = tid >> 4;

    if (tid < BM) toks[tid] = tokens[m0 + tid];
    __syncthreads();

    unsigned long long acc[4][4];
#pragma unroll
    for (int i = 0; i < 4; i++)
#pragma unroll
        for (int j = 0; j < 4; j++) acc[i][j] = 0ull;

    for (int k0 = 0; k0 < EE; k0 += BK) {
#pragma unroll
        for (int i = 0; i < 2; i++) {
            int id = tid * 2 + i;
            int m  = id >> 2;
            int kg = id & 3;
            float4 v = *(const float4*)(emb + (size_t)toks[m] * EE + k0 + kg * 4);
            As[kg*4+0][m] = v.x; As[kg*4+1][m] = v.y;
            As[kg*4+2][m] = v.z; As[kg*4+3][m] = v.w;
        }
        {
            int k = tid >> 4, ng = tid & 15;
            *(float4*)&Bs[k][ng*4] =
                *(const float4*)(Wp + (size_t)(k0 + k) * U3 + n0 + ng * 4);
        }
        __syncthreads();
#pragma unroll
        for (int k = 0; k < BK; k++) {
            ulonglong2 a01 = *(const ulonglong2*)&As[k][ty*8];
            ulonglong2 a23 = *(const ulonglong2*)&As[k][ty*8+4];
            float4 b4 = *(const float4*)&Bs[k][tx*4];
            unsigned long long ap[4] = {a01.x, a01.y, a23.x, a23.y};
            unsigned long long bp2[4] = {dup2(b4.x), dup2(b4.y), dup2(b4.z), dup2(b4.w)};
#pragma unroll
            for (int i = 0; i < 4; i++)
#pragma unroll
                for (int j = 0; j < 4; j++)
                    acc[i][j] = ffma2(ap[i], bp2[j], acc[i][j]);
        }
        __syncthreads();
    }

    float4 bias = *(const float4*)(bp + n0 + tx * 4);
    float* gx = &g_xproj[0][0][0][0];
#pragma unroll
    for (int i = 0; i < 4; i++) {
        float2 c0 = unpack2(acc[i][0]);
        float2 c1 = unpack2(acc[i][1]);
        float2 c2 = unpack2(acc[i][2]);
        float2 c3 = unpack2(acc[i][3]);
        size_t mlo = (size_t)(m0 + ty * 8 + i * 2);
        float4 vlo = { c0.x + bias.x, c1.x + bias.y, c2.x + bias.z, c3.x + bias.w };
        float4 vhi = { c0.y + bias.x, c1.y + bias.y, c2.y + bias.z, c3.y + bias.w };
        *(float4*)(gx + ((size_t)d * (BB*TT) + mlo)     * U3 + n0 + tx * 4) = vlo;
        *(float4*)(gx + ((size_t)d * (BB*TT) + mlo + 1) * U3 + n0 + tx * 4) = vhi;
    }
}

// ---------------- Kernel B: persistent GRU recurrence (tf32 tensor cores) ---
// 128 blocks (64/dir), 256 threads = 8 warps = (2 m-tiles x 4 k-splits).
// P[32x24] = H[32x512] * U[512x24] via m16n8k8.tf32, 2-way split,
// 9 independent acc sets (3 n-tiles x {hi*hi, hi*lo, lo*hi}) -> chains of 16.
// One-phase k reduction: psum[24][32][4slots], summed by epilogue threads.
// Flag-array global barrier (parallel 64-flag poll, no atomics).
#define GRU_SMEM_FLOATS (32*PADK + 2*24*PK2 + 24*PSC + 512)
#define SMEM_BYTES (GRU_SMEM_FLOATS * 4)

__global__ void __launch_bounds__(256, 1) gru_kernel(
    const int* __restrict__ tokens,
    const float* __restrict__ U_fw, const float* __restrict__ b_rec_fw,
    const float* __restrict__ U_bw, const float* __restrict__ b_rec_bw,
    float* __restrict__ out)
{
    extern __shared__ float smem[];
    float*    hs    = smem;                       // [32][516] h (fp32)
    float2*   UsP   = (float2*)(hs + 32*PADK);    // [24][521] {hi, lo}
    float*    psum  = (float*)(UsP + 24*PK2);     // [24 cols][32 b][4 slots] strides 164/5
    unsigned* maskw = (unsigned*)(psum + 24*PSC); // [32][16] mask bits

    const int bid = blockIdx.x;
    const int d   = bid >> 6;
    const int jb  = bid & (NBLK - 1);
    const int u0  = jb * 8;
    const int tid = threadIdx.x;
    const int wid = tid >> 5;
    const int lane = tid & 31;
    const int mi = wid & 1;          // m-tile (rows mi*16 .. +15)
    const int kh = wid >> 1;         // k-split 0..3 (range kh*128 .. +128)
    const int gr = lane >> 2;        // fragment group row
    const int gc = lane & 3;         // fragment group col

    const float* __restrict__ Uw = d ? U_bw : U_fw;
    const float* __restrict__ br = d ? b_rec_bw : b_rec_fw;

    // stage U hi/lo once (reused all 512 steps)
    for (int idx = tid; idx < 24 * 512; idx += 256) {
        int c = idx >> 9;            // col 0..23 (c = g*8 + ul)
        int k = idx & 511;
        int g = c >> 3;
        float v = Uw[(size_t)k * U3 + g * 512 + u0 + (c & 7)];
        float hi = __uint_as_float(tf32_hi_bits(v));
        UsP[c * PK2 + k] = make_float2(hi, v - hi);
    }
    // mask bitmap: maskw[b][w] bit i = (tokens[b, w*32+i] != 0)
    for (int i = tid; i < 512; i += 256) {
        int b = i >> 4, w = i & 15;
        unsigned m = 0;
        const int* tp = tokens + b * TT + w * 32;
#pragma unroll 8
        for (int q = 0; q < 32; q++) m |= (tp[q] != 0 ? (1u << q) : 0u);
        maskw[b * 16 + w] = m;
    }

    // epilogue mapping (all 256 threads): batch eb, unit eu
    const int eb = tid >> 3, eu = tid & 7;
    const float brz = br[0*512 + u0 + eu];
    const float brr = br[1*512 + u0 + eu];
    const float brh = br[2*512 + u0 + eu];

    const float* gx = &g_xproj[0][0][0][0];

    const int rA0 = (mi*16 + gr) * PADK + gc;   // A frag rows gr / gr+8
    const int rA1 = rA0 + 8 * PADK;
    const int r0  = mi*16 + gr;
    const int r1  = r0 + 8;
    const int kbase = kh * 128;

    __syncthreads();

    for (int ts = 0; ts < TT; ts++) {
        const int t   = d ? (TT - 1 - ts) : ts;
        const int buf = ts & 1;

        // stage h_prev into padded SMEM rows (16 float4 per thread)
        const float4* hp_g = (const float4*)&g_h[d][buf][0][0];
#pragma unroll
        for (int i = 0; i < 16; i++) {
            int id  = tid + i * 256;       // 0..4095 float4 slots
            int row = id >> 7;
            int q   = id & 127;
            *(float4*)&hs[row * PADK + q * 4] = hp_g[id];
        }
        // prefetch epilogue inputs (latency hidden under sync + dot)
        size_t xb = ((size_t)d * (BB*TT) + (size_t)eb * TT + t) * U3;
        float xz = gx[xb + u0 + eu];
        float xr = gx[xb + 512 + u0 + eu];
        float xh = gx[xb + 1024 + u0 + eu];
        __syncthreads();

        // ---- tensor-core dot: 16 k-tiles, 3 n-tiles, 9 independent acc sets
        float Dhh[3][4], Dhl[3][4], Dlh[3][4];
#pragma unroll
        for (int j = 0; j < 3; j++)
#pragma unroll
            for (int q = 0; q < 4; q++) { Dhh[j][q] = 0.f; Dhl[j][q] = 0.f; Dlh[j][q] = 0.f; }

#pragma unroll 4
        for (int kt = 0; kt < 16; kt++) {
            int k0 = kbase + kt * 8;
            float f0 = hs[rA0 + k0];
            float f1 = hs[rA1 + k0];
            float f2 = hs[rA0 + k0 + 4];
            float f3 = hs[rA1 + k0 + 4];
            unsigned a0h = tf32_hi_bits(f0);
            unsigned a1h = tf32_hi_bits(f1);
            unsigned a2h = tf32_hi_bits(f2);
            unsigned a3h = tf32_hi_bits(f3);
            unsigned a0l = __float_as_uint(f0 - __uint_as_float(a0h));
            unsigned a1l = __float_as_uint(f1 - __uint_as_float(a1h));
            unsigned a2l = __float_as_uint(f2 - __uint_as_float(a2h));
            unsigned a3l = __float_as_uint(f3 - __uint_as_float(a3h));
#pragma unroll
            for (int j = 0; j < 3; j++) {
                const float2* bp2 = UsP + (j*8 + gr) * PK2 + k0 + gc;
                float2 blo = bp2[0];     // {hi, lo} at k0+gc
                float2 bhi = bp2[4];     // {hi, lo} at k0+gc+4
                unsigned b0 = __float_as_uint(blo.x);
                unsigned b1 = __float_as_uint(bhi.x);
                unsigned c0 = __float_as_uint(blo.y);
                unsigned c1 = __float_as_uint(bhi.y);
                mma_tf32(Dhh[j][0], Dhh[j][1], Dhh[j][2], Dhh[j][3],
                         a0h, a1h, a2h, a3h, b0, b1);
                mma_tf32(Dhl[j][0], Dhl[j][1], Dhl[j][2], Dhl[j][3],
                         a0h, a1h, a2h, a3h, c0, c1);
                mma_tf32(Dlh[j][0], Dlh[j][1], Dlh[j][2], Dlh[j][3],
                         a0l, a1l, a2l, a3l, b0, b1);
            }
        }

        // combine splits and publish k-partials (slot = kh)
#pragma unroll
        for (int j = 0; j < 3; j++) {
            float d0 = Dhh[j][0] + Dhl[j][0] + Dlh[j][0];
            float d1 = Dhh[j][1] + Dhl[j][1] + Dlh[j][1];
            float d2 = Dhh[j][2] + Dhl[j][2] + Dlh[j][2];
            float d3 = Dhh[j][3] + Dhl[j][3] + Dlh[j][3];
            int c0 = j*8 + gc*2, c1 = c0 + 1;
            psum[c0*PSC + r0*PSB + kh] = d0;
            psum[c1*PSC + r0*PSB + kh] = d1;
            psum[c0*PSC + r1*PSB + kh] = d2;
            psum[c1*PSC + r1*PSB + kh] = d3;
        }
        __syncthreads();

        // ---- epilogue: all 256 threads, each = one (batch, unit) ----
        {
            const float* pz = psum + (0*8 + eu)*PSC + eb*PSB;
            const float* pr = psum + (1*8 + eu)*PSC + eb*PSB;
            const float* ph = psum + (2*8 + eu)*PSC + eb*PSB;
            float hz = brz + ((pz[0] + pz[1]) + (pz[2] + pz[3]));
            float hr = brr + ((pr[0] + pr[1]) + (pr[2] + pr[3]));
            float hh = brh + ((ph[0] + ph[1]) + (ph[2] + ph[3]));

            float z    = 1.f / (1.f + expf(-(xz + hz)));
            float r    = 1.f / (1.f + expf(-(xr + hr)));
            float cand = tanhf(xh + r * hh);
            float hp   = hs[eb * PADK + u0 + eu];
            float hn   = z * hp + (1.f - z) * cand;
            if (!((maskw[eb * 16 + (t >> 5)] >> (t & 31)) & 1u)) hn = hp;

            g_h[d][buf ^ 1][eb][u0 + eu] = hn;
            out[((size_t)eb * TT + t) * (2*UU) + (size_t)d * UU + u0 + eu] = hn;
        }

        // ---- flag-array inter-block barrier (per direction, per step) ----
        if (ts + 1 < TT) {
            __syncthreads();                       // h writes issued by all threads
            if (tid == 0) {
                __threadfence();                   // release: h visible before flag
                g_flag[d][ts][jb] = 1u;
            }
            if (tid < NBLK) {
                volatile unsigned* f = &g_flag[d][ts][tid];
                while (*f == 0u) { }
            }
            __syncthreads();                       // all flags observed
            if (tid == 0) __threadfence();         // acquire: invalidate L1 before h reads
            __syncthreads();
        }
    }
}

// ---------------- launch ----------------------------------------------------
extern "C" void kernel_launch(void* const* d_in, const int* in_sizes, int n_in,
                              void* d_out, int out_size)
{
    const int*   tokens   = (const int*)  d_in[0];
    const float* emb      = (const float*)d_in[1];
    const float* W_fw     = (const float*)d_in[2];
    const float* U_fw     = (const float*)d_in[3];
    const float* b_in_fw  = (const float*)d_in[4];
    const float* b_rec_fw = (const float*)d_in[5];
    const float* W_bw     = (const float*)d_in[6];
    const float* U_bw     = (const float*)d_in[7];
    const float* b_in_bw  = (const float*)d_in[8];
    const float* b_rec_bw = (const float*)d_in[9];
    float* out = (float*)d_out;

    void* p;
    cudaGetSymbolAddress(&p, g_h);
    cudaMemsetAsync(p, 0, sizeof(g_h));
    cudaGetSymbolAddress(&p, g_flag);
    cudaMemsetAsync(p, 0, sizeof(g_flag));

    dim3 gA(U3 / BN, (BB * TT) / BM, 2);
    xproj_kernel<<<gA, 256>>>(tokens, emb, W_fw, b_in_fw, W_bw, b_in_bw);

    cudaFuncSetAttribute(gru_kernel,
                         cudaFuncAttributeMaxDynamicSharedMemorySize, SMEM_BYTES);
    gru_kernel<<<RGRID, 256, SMEM_BYTES>>>(tokens, U_fw, b_rec_fw,
                                           U_bw, b_rec_bw, out);
}

// round 8
// speedup vs baseline: 1.4629x; 1.4629x over previous
#include <cuda_runtime.h>
#include <math.h>
#include <stdint.h>

#define BB 32
#define TT 512
#define EE 256
#define UU 512
#define U3 1536
#define NBLK 64          // blocks per direction in recurrence
#define RGRID (2*NBLK)   // total recurrence blocks
#define PADK 516         // padded k-stride for h rows (conflict-free LDS)
#define PK2  521         // float2 stride for U hi/lo (conflict-free LDS.64)
#define PSB  5           // psum batch stride (4 slots + pad)
#define PSC  164         // psum col stride (32*5 + pad, conflict-free epilogue)
#define NCNT 4           // barrier counters per step (16 arrivals each)

// ---------------- device scratch (static; no runtime allocation) ------------
__device__ float    g_xproj[2][BB][TT][U3];   // x@W + b_in per direction
__device__ float    g_h[2][2][BB][UU];        // [dir][buf][b][u] double-buffered state
__device__ unsigned g_cnt[2][TT][NCNT];       // per-step barrier counters (memset to 0)

// ---------------- packed f32x2 helpers (xproj kernel) -----------------------
__device__ __forceinline__ unsigned long long ffma2(unsigned long long a,
                                                    unsigned long long b,
                                                    unsigned long long c) {
    unsigned long long d;
    asm("fma.rn.f32x2 %0, %1, %2, %3;" : "=l"(d) : "l"(a), "l"(b), "l"(c));
    return d;
}
__device__ __forceinline__ unsigned long long dup2(float x) {
    unsigned long long d;
    asm("mov.b64 %0, {%1, %1};" : "=l"(d) : "f"(x));
    return d;
}
__device__ __forceinline__ float2 unpack2(unsigned long long v) {
    float2 r;
    asm("mov.b64 {%0, %1}, %2;" : "=f"(r.x), "=f"(r.y) : "l"(v));
    return r;
}

// ---------------- tf32 mma helper -------------------------------------------
__device__ __forceinline__ void mma_tf32(float& d0, float& d1, float& d2, float& d3,
                                         unsigned a0, unsigned a1, unsigned a2, unsigned a3,
                                         unsigned b0, unsigned b1) {
    asm volatile(
        "mma.sync.aligned.m16n8k8.row.col.f32.tf32.tf32.f32 "
        "{%0,%1,%2,%3}, {%4,%5,%6,%7}, {%8,%9}, {%0,%1,%2,%3};"
        : "+f"(d0), "+f"(d1), "+f"(d2), "+f"(d3)
        : "r"(a0), "r"(a1), "r"(a2), "r"(a3), "r"(b0), "r"(b1));
}
__device__ __forceinline__ unsigned tf32_hi_bits(float x) {
    return __float_as_uint(x) & 0xFFFFE000u;
}

// ---------------- Kernel A: x_proj = emb[tokens] @ W + b_in -----------------
#define BM 128
#define BN 64
#define BK 16

__global__ void __launch_bounds__(256) xproj_kernel(
    const int* __restrict__ tokens,
    const float* __restrict__ emb,
    const float* __restrict__ W_fw, const float* __restrict__ b_in_fw,
    const float* __restrict__ W_bw, const float* __restrict__ b_in_bw)
{
    __shared__ __align__(16) float As[BK][BM];
    __shared__ __align__(16) float Bs[BK][BN];
    __shared__ int toks[BM];

    const int d  = blockIdx.z;
    const float* __restrict__ Wp = d ? W_bw : W_fw;
    const float* __restrict__ bp = d ? b_in_bw : b_in_fw;
    const int n0 = blockIdx.x * BN;
    const int m0 = blockIdx.y * BM;
    const int tid = threadIdx.x;
    const int tx = tid & 15;
    const int ty = tid >> 4;

    if (tid < BM) toks[tid] = tokens[m0 + tid];
    __syncthreads();

    unsigned long long acc[4][4];
#pragma unroll
    for (int i = 0; i < 4; i++)
#pragma unroll
        for (int j = 0; j < 4; j++) acc[i][j] = 0ull;

    for (int k0 = 0; k0 < EE; k0 += BK) {
#pragma unroll
        for (int i = 0; i < 2; i++) {
            int id = tid * 2 + i;
            int m  = id >> 2;
            int kg = id & 3;
            float4 v = *(const float4*)(emb + (size_t)toks[m] * EE + k0 + kg * 4);
            As[kg*4+0][m] = v.x; As[kg*4+1][m] = v.y;
            As[kg*4+2][m] = v.z; As[kg*4+3][m] = v.w;
        }
        {
            int k = tid >> 4, ng = tid & 15;
            *(float4*)&Bs[k][ng*4] =
                *(const float4*)(Wp + (size_t)(k0 + k) * U3 + n0 + ng * 4);
        }
        __syncthreads();
#pragma unroll
        for (int k = 0; k < BK; k++) {
            ulonglong2 a01 = *(const ulonglong2*)&As[k][ty*8];
            ulonglong2 a23 = *(const ulonglong2*)&As[k][ty*8+4];
            float4 b4 = *(const float4*)&Bs[k][tx*4];
            unsigned long long ap[4] = {a01.x, a01.y, a23.x, a23.y};
            unsigned long long bp2[4] = {dup2(b4.x), dup2(b4.y), dup2(b4.z), dup2(b4.w)};
#pragma unroll
            for (int i = 0; i < 4; i++)
#pragma unroll
                for (int j = 0; j < 4; j++)
                    acc[i][j] = ffma2(ap[i], bp2[j], acc[i][j]);
        }
        __syncthreads();
    }

    float4 bias = *(const float4*)(bp + n0 + tx * 4);
    float* gx = &g_xproj[0][0][0][0];
#pragma unroll
    for (int i = 0; i < 4; i++) {
        float2 c0 = unpack2(acc[i][0]);
        float2 c1 = unpack2(acc[i][1]);
        float2 c2 = unpack2(acc[i][2]);
        float2 c3 = unpack2(acc[i][3]);
        size_t mlo = (size_t)(m0 + ty * 8 + i * 2);
        float4 vlo = { c0.x + bias.x, c1.x + bias.y, c2.x + bias.z, c3.x + bias.w };
        float4 vhi = { c0.y + bias.x, c1.y + bias.y, c2.y + bias.z, c3.y + bias.w };
        *(float4*)(gx + ((size_t)d * (BB*TT) + mlo)     * U3 + n0 + tx * 4) = vlo;
        *(float4*)(gx + ((size_t)d * (BB*TT) + mlo + 1) * U3 + n0 + tx * 4) = vhi;
    }
}

// ---------------- Kernel B: persistent GRU recurrence (tf32 tensor cores) ---
// 128 blocks (64/dir), 256 threads = 8 warps = (2 m-tiles x 4 k-splits).
// P[32x24] = H[32x512] * U[512x24] via m16n8k8.tf32, 2-way split,
// 9 independent acc sets (3 n-tiles x {hi*hi, hi*lo, lo*hi}) -> chains of 16.
// One-phase k reduction: psum[24][32][4slots], summed by epilogue threads.
// Global barrier: 4 split atomic counters (16 arrivals each), 4 pollers.
#define GRU_SMEM_FLOATS (32*PADK + 2*24*PK2 + 24*PSC + 512)
#define SMEM_BYTES (GRU_SMEM_FLOATS * 4)

__global__ void __launch_bounds__(256, 1) gru_kernel(
    const int* __restrict__ tokens,
    const float* __restrict__ U_fw, const float* __restrict__ b_rec_fw,
    const float* __restrict__ U_bw, const float* __restrict__ b_rec_bw,
    float* __restrict__ out)
{
    extern __shared__ float smem[];
    float*    hs    = smem;                       // [32][516] h (fp32)
    float2*   UsP   = (float2*)(hs + 32*PADK);    // [24][521] {hi, lo}
    float*    psum  = (float*)(UsP + 24*PK2);     // [24 cols][32 b][4 slots]
    unsigned* maskw = (unsigned*)(psum + 24*PSC); // [32][16] mask bits

    const int bid = blockIdx.x;
    const int d   = bid >> 6;
    const int jb  = bid & (NBLK - 1);
    const int u0  = jb * 8;
    const int tid = threadIdx.x;
    const int wid = tid >> 5;
    const int lane = tid & 31;
    const int mi = wid & 1;          // m-tile (rows mi*16 .. +15)
    const int kh = wid >> 1;         // k-split 0..3 (range kh*128 .. +128)
    const int gr = lane >> 2;        // fragment group row
    const int gc = lane & 3;         // fragment group col

    const float* __restrict__ Uw = d ? U_bw : U_fw;
    const float* __restrict__ br = d ? b_rec_bw : b_rec_fw;

    // stage U hi/lo once (reused all 512 steps)
    for (int idx = tid; idx < 24 * 512; idx += 256) {
        int c = idx >> 9;            // col 0..23 (c = g*8 + ul)
        int k = idx & 511;
        int g = c >> 3;
        float v = Uw[(size_t)k * U3 + g * 512 + u0 + (c & 7)];
        float hi = __uint_as_float(tf32_hi_bits(v));
        UsP[c * PK2 + k] = make_float2(hi, v - hi);
    }
    // mask bitmap: maskw[b][w] bit i = (tokens[b, w*32+i] != 0)
    for (int i = tid; i < 512; i += 256) {
        int b = i >> 4, w = i & 15;
        unsigned m = 0;
        const int* tp = tokens + b * TT + w * 32;
#pragma unroll 8
        for (int q = 0; q < 32; q++) m |= (tp[q] != 0 ? (1u << q) : 0u);
        maskw[b * 16 + w] = m;
    }

    // epilogue mapping (all 256 threads): batch eb, unit eu
    const int eb = tid >> 3, eu = tid & 7;
    const float brz = br[0*512 + u0 + eu];
    const float brr = br[1*512 + u0 + eu];
    const float brh = br[2*512 + u0 + eu];

    const float* gx = &g_xproj[0][0][0][0];

    const int rA0 = (mi*16 + gr) * PADK + gc;   // A frag rows gr / gr+8
    const int rA1 = rA0 + 8 * PADK;
    const int r0  = mi*16 + gr;
    const int r1  = r0 + 8;
    const int kbase = kh * 128;

    __syncthreads();

    for (int ts = 0; ts < TT; ts++) {
        const int t   = d ? (TT - 1 - ts) : ts;
        const int buf = ts & 1;

        // stage h_prev into padded SMEM rows (16 float4 per thread)
        const float4* hp_g = (const float4*)&g_h[d][buf][0][0];
#pragma unroll
        for (int i = 0; i < 16; i++) {
            int id  = tid + i * 256;       // 0..4095 float4 slots
            int row = id >> 7;
            int q   = id & 127;
            *(float4*)&hs[row * PADK + q * 4] = hp_g[id];
        }
        // prefetch epilogue inputs (latency hidden under sync + dot)
        size_t xb = ((size_t)d * (BB*TT) + (size_t)eb * TT + t) * U3;
        float xz = gx[xb + u0 + eu];
        float xr = gx[xb + 512 + u0 + eu];
        float xh = gx[xb + 1024 + u0 + eu];
        __syncthreads();

        // ---- tensor-core dot: 16 k-tiles, 3 n-tiles, 9 independent acc sets
        float Dhh[3][4], Dhl[3][4], Dlh[3][4];
#pragma unroll
        for (int j = 0; j < 3; j++)
#pragma unroll
            for (int q = 0; q < 4; q++) { Dhh[j][q] = 0.f; Dhl[j][q] = 0.f; Dlh[j][q] = 0.f; }

#pragma unroll 4
        for (int kt = 0; kt < 16; kt++) {
            int k0 = kbase + kt * 8;
            float f0 = hs[rA0 + k0];
            float f1 = hs[rA1 + k0];
            float f2 = hs[rA0 + k0 + 4];
            float f3 = hs[rA1 + k0 + 4];
            unsigned a0h = tf32_hi_bits(f0);
            unsigned a1h = tf32_hi_bits(f1);
            unsigned a2h = tf32_hi_bits(f2);
            unsigned a3h = tf32_hi_bits(f3);
            unsigned a0l = __float_as_uint(f0 - __uint_as_float(a0h));
            unsigned a1l = __float_as_uint(f1 - __uint_as_float(a1h));
            unsigned a2l = __float_as_uint(f2 - __uint_as_float(a2h));
            unsigned a3l = __float_as_uint(f3 - __uint_as_float(a3h));
#pragma unroll
            for (int j = 0; j < 3; j++) {
                const float2* bp2 = UsP + (j*8 + gr) * PK2 + k0 + gc;
                float2 blo = bp2[0];     // {hi, lo} at k0+gc
                float2 bhi = bp2[4];     // {hi, lo} at k0+gc+4
                unsigned b0 = __float_as_uint(blo.x);
                unsigned b1 = __float_as_uint(bhi.x);
                unsigned c0 = __float_as_uint(blo.y);
                unsigned c1 = __float_as_uint(bhi.y);
                mma_tf32(Dhh[j][0], Dhh[j][1], Dhh[j][2], Dhh[j][3],
                         a0h, a1h, a2h, a3h, b0, b1);
                mma_tf32(Dhl[j][0], Dhl[j][1], Dhl[j][2], Dhl[j][3],
                         a0h, a1h, a2h, a3h, c0, c1);
                mma_tf32(Dlh[j][0], Dlh[j][1], Dlh[j][2], Dlh[j][3],
                         a0l, a1l, a2l, a3l, b0, b1);
            }
        }

        // combine splits and publish k-partials (slot = kh)
#pragma unroll
        for (int j = 0; j < 3; j++) {
            float d0 = Dhh[j][0] + Dhl[j][0] + Dlh[j][0];
            float d1 = Dhh[j][1] + Dhl[j][1] + Dlh[j][1];
            float d2 = Dhh[j][2] + Dhl[j][2] + Dlh[j][2];
            float d3 = Dhh[j][3] + Dhl[j][3] + Dlh[j][3];
            int c0 = j*8 + gc*2, c1 = c0 + 1;
            psum[c0*PSC + r0*PSB + kh] = d0;
            psum[c1*PSC + r0*PSB + kh] = d1;
            psum[c0*PSC + r1*PSB + kh] = d2;
            psum[c1*PSC + r1*PSB + kh] = d3;
        }
        __syncthreads();

        // ---- epilogue: all 256 threads, each = one (batch, unit) ----
        {
            const float* pz = psum + (0*8 + eu)*PSC + eb*PSB;
            const float* pr = psum + (1*8 + eu)*PSC + eb*PSB;
            const float* ph = psum + (2*8 + eu)*PSC + eb*PSB;
            float hz = brz + ((pz[0] + pz[1]) + (pz[2] + pz[3]));
            float hr = brr + ((pr[0] + pr[1]) + (pr[2] + pr[3]));
            float hh = brh + ((ph[0] + ph[1]) + (ph[2] + ph[3]));

            float z    = 1.f / (1.f + expf(-(xz + hz)));
            float r    = 1.f / (1.f + expf(-(xr + hr)));
            float cand = tanhf(xh + r * hh);
            float hp   = hs[eb * PADK + u0 + eu];
            float hn   = z * hp + (1.f - z) * cand;
            if (!((maskw[eb * 16 + (t >> 5)] >> (t & 31)) & 1u)) hn = hp;

            g_h[d][buf ^ 1][eb][u0 + eu] = hn;
            out[((size_t)eb * TT + t) * (2*UU) + (size_t)d * UU + u0 + eu] = hn;
        }

        // ---- split-counter inter-block barrier (per direction, per step) ----
        if (ts + 1 < TT) {
            __syncthreads();
            if (tid == 0) {
                __threadfence();                          // release h writes
                atomicAdd(&g_cnt[d][ts][jb & (NCNT-1)], 1u);
            }
            if (tid < NCNT) {
                volatile unsigned* c = &g_cnt[d][ts][tid];
                while (*c < (NBLK / NCNT)) { }
            }
            __syncthreads();                              // all counters observed
            if (tid == 0) __threadfence();                // acquire / L1 invalidate
            __syncthreads();
        }
    }
}

// ---------------- launch ----------------------------------------------------
extern "C" void kernel_launch(void* const* d_in, const int* in_sizes, int n_in,
                              void* d_out, int out_size)
{
    const int*   tokens   = (const int*)  d_in[0];
    const float* emb      = (const float*)d_in[1];
    const float* W_fw     = (const float*)d_in[2];
    const float* U_fw     = (const float*)d_in[3];
    const float* b_in_fw  = (const float*)d_in[4];
    const float* b_rec_fw = (const float*)d_in[5];
    const float* W_bw     = (const float*)d_in[6];
    const float* U_bw     = (const float*)d_in[7];
    const float* b_in_bw  = (const float*)d_in[8];
    const float* b_rec_bw = (const float*)d_in[9];
    float* out = (float*)d_out;

    void* p;
    cudaGetSymbolAddress(&p, g_h);
    cudaMemsetAsync(p, 0, sizeof(g_h));
    cudaGetSymbolAddress(&p, g_cnt);
    cudaMemsetAsync(p, 0, sizeof(g_cnt));

    dim3 gA(U3 / BN, (BB * TT) / BM, 2);
    xproj_kernel<<<gA, 256>>>(tokens, emb, W_fw, b_in_fw, W_bw, b_in_bw);

    cudaFuncSetAttribute(gru_kernel,
                         cudaFuncAttributeMaxDynamicSharedMemorySize, SMEM_BYTES);
    gru_kernel<<<RGRID, 256, SMEM_BYTES>>>(tokens, U_fw, b_rec_fw,
                                           U_bw, b_rec_bw, out);
}

// round 9
// speedup vs baseline: 1.7861x; 1.2210x over previous
#include <cuda_runtime.h>
#include <cuda_bf16.h>
#include <math.h>
#include <stdint.h>

#define BB 32
#define TT 512
#define EE 256
#define UU 512
#define U3 1536
#define NBLK 64          // blocks per direction in recurrence
#define RGRID (2*NBLK)   // total recurrence blocks
#define PADW 520         // padded word-stride for packed rows/cols

// ---------------- device scratch (static; no runtime allocation) ------------
__device__ float    g_xproj[2][BB][TT][U3];   // x@W + b_in per direction
__device__ unsigned g_h[2][2][BB][UU];        // packed {lo,hi} bf16 state, double-buffered
__device__ unsigned g_cnt[2][TT];             // per-step barrier counters (memset to 0)

// ---------------- packed f32x2 helpers (xproj kernel) -----------------------
__device__ __forceinline__ unsigned long long ffma2(unsigned long long a,
                                                    unsigned long long b,
                                                    unsigned long long c) {
    unsigned long long d;
    asm("fma.rn.f32x2 %0, %1, %2, %3;" : "=l"(d) : "l"(a), "l"(b), "l"(c));
    return d;
}
__device__ __forceinline__ unsigned long long dup2(float x) {
    unsigned long long d;
    asm("mov.b64 %0, {%1, %1};" : "=l"(d) : "f"(x));
    return d;
}
__device__ __forceinline__ float2 unpack2(unsigned long long v) {
    float2 r;
    asm("mov.b64 {%0, %1}, %2;" : "=f"(r.x), "=f"(r.y) : "l"(v));
    return r;
}

// ---------------- bf16 split helpers ----------------------------------------
// word layout: low 16 = hi bf16, high 16 = lo bf16 (lo = bf16(v - float(hi)))
__device__ __forceinline__ unsigned split_pack(float v) {
    unsigned short h = __bfloat16_as_ushort(__float2bfloat16_rn(v));
    float fh = __uint_as_float((unsigned)h << 16);
    unsigned short l = __bfloat16_as_ushort(__float2bfloat16_rn(v - fh));
    return ((unsigned)l << 16) | (unsigned)h;
}
__device__ __forceinline__ float unsplit(unsigned w) {
    return __uint_as_float(w << 16) + __uint_as_float(w & 0xFFFF0000u);
}
__device__ __forceinline__ unsigned prmt(unsigned a, unsigned b, unsigned sel) {
    unsigned d;
    asm("prmt.b32 %0, %1, %2, %3;" : "=r"(d) : "r"(a), "r"(b), "r"(sel));
    return d;
}

// ---------------- bf16 mma helper (m16n8k16) ---------------------------------
__device__ __forceinline__ void mma_bf16(float* D,
                                         unsigned a0, unsigned a1, unsigned a2, unsigned a3,
                                         unsigned b0, unsigned b1) {
    asm volatile(
        "mma.sync.aligned.m16n8k16.row.col.f32.bf16.bf16.f32 "
        "{%0,%1,%2,%3}, {%4,%5,%6,%7}, {%8,%9}, {%0,%1,%2,%3};"
        : "+f"(D[0]), "+f"(D[1]), "+f"(D[2]), "+f"(D[3])
        : "r"(a0), "r"(a1), "r"(a2), "r"(a3), "r"(b0), "r"(b1));
}

// ---------------- Kernel A: x_proj = emb[tokens] @ W + b_in -----------------
#define BM 128
#define BN 64
#define BK 16

__global__ void __launch_bounds__(256) xproj_kernel(
    const int* __restrict__ tokens,
    const float* __restrict__ emb,
    const float* __restrict__ W_fw, const float* __restrict__ b_in_fw,
    const float* __restrict__ W_bw, const float* __restrict__ b_in_bw)
{
    __shared__ __align__(16) float As[BK][BM];
    __shared__ __align__(16) float Bs[BK][BN];
    __shared__ int toks[BM];

    const int d  = blockIdx.z;
    const float* __restrict__ Wp = d ? W_bw : W_fw;
    const float* __restrict__ bp = d ? b_in_bw : b_in_fw;
    const int n0 = blockIdx.x * BN;
    const int m0 = blockIdx.y * BM;
    const int tid = threadIdx.x;
    const int tx = tid & 15;
    const int ty = tid >> 4;

    if (tid < BM) toks[tid] = tokens[m0 + tid];
    __syncthreads();

    unsigned long long acc[4][4];
#pragma unroll
    for (int i = 0; i < 4; i++)
#pragma unroll
        for (int j = 0; j < 4; j++) acc[i][j] = 0ull;

    for (int k0 = 0; k0 < EE; k0 += BK) {
#pragma unroll
        for (int i = 0; i < 2; i++) {
            int id = tid * 2 + i;
            int m  = id >> 2;
            int kg = id & 3;
            float4 v = *(const float4*)(emb + (size_t)toks[m] * EE + k0 + kg * 4);
            As[kg*4+0][m] = v.x; As[kg*4+1][m] = v.y;
            As[kg*4+2][m] = v.z; As[kg*4+3][m] = v.w;
        }
        {
            int k = tid >> 4, ng = tid & 15;
            *(float4*)&Bs[k][ng*4] =
                *(const float4*)(Wp + (size_t)(k0 + k) * U3 + n0 + ng * 4);
        }
        __syncthreads();
#pragma unroll
        for (int k = 0; k < BK; k++) {
            ulonglong2 a01 = *(const ulonglong2*)&As[k][ty*8];
            ulonglong2 a23 = *(const ulonglong2*)&As[k][ty*8+4];
            float4 b4 = *(const float4*)&Bs[k][tx*4];
            unsigned long long ap[4] = {a01.x, a01.y, a23.x, a23.y};
            unsigned long long bp2[4] = {dup2(b4.x), dup2(b4.y), dup2(b4.z), dup2(b4.w)};
#pragma unroll
            for (int i = 0; i < 4; i++)
#pragma unroll
                for (int j = 0; j < 4; j++)
                    acc[i][j] = ffma2(ap[i], bp2[j], acc[i][j]);
        }
        __syncthreads();
    }

    float4 bias = *(const float4*)(bp + n0 + tx * 4);
    float* gx = &g_xproj[0][0][0][0];
#pragma unroll
    for (int i = 0; i < 4; i++) {
        float2 c0 = unpack2(acc[i][0]);
        float2 c1 = unpack2(acc[i][1]);
        float2 c2 = unpack2(acc[i][2]);
        float2 c3 = unpack2(acc[i][3]);
        size_t mlo = (size_t)(m0 + ty * 8 + i * 2);
        float4 vlo = { c0.x + bias.x, c1.x + bias.y, c2.x + bias.z, c3.x + bias.w };
        float4 vhi = { c0.y + bias.x, c1.y + bias.y, c2.y + bias.z, c3.y + bias.w };
        *(float4*)(gx + ((size_t)d * (BB*TT) + mlo)     * U3 + n0 + tx * 4) = vlo;
        *(float4*)(gx + ((size_t)d * (BB*TT) + mlo + 1) * U3 + n0 + tx * 4) = vhi;
    }
}

// ---------------- Kernel B: persistent GRU recurrence (bf16x3 tensor cores) -
// R5 skeleton: 128 blocks (64/dir), 256 threads = 8 warps = (2 m x 4 k-splits),
// two-phase psum, single-counter barrier. Dot swapped to m16n8k16.bf16 with
// packed {hi,lo} bf16 words for h and U (split at write time, PRMT at read).
// SMEM words: hs 32*520 + Us 24*520 ; psum floats 3*32*24.
#define SMEM_BYTES ((32*PADW + 24*PADW + 3*32*24 + 64) * 4)

__global__ void __launch_bounds__(256, 1) gru_kernel(
    const int* __restrict__ tokens,
    const float* __restrict__ U_fw, const float* __restrict__ b_rec_fw,
    const float* __restrict__ U_bw, const float* __restrict__ b_rec_bw,
    float* __restrict__ out)
{
    extern __shared__ unsigned smemw[];
    unsigned* hsW  = smemw;                    // [32][520] packed h words
    unsigned* UsW  = hsW + 32*PADW;            // [24][520] packed U words
    float*    psum = (float*)(UsW + 24*PADW);  // [3][32][24] float

    const int bid = blockIdx.x;
    const int d   = bid >> 6;
    const int jb  = bid & (NBLK - 1);
    const int u0  = jb * 8;
    const int tid = threadIdx.x;
    const int wid = tid >> 5;
    const int lane = tid & 31;
    const int mi = wid & 1;          // m-tile (rows mi*16 .. +15)
    const int kh = wid >> 1;         // k-split 0..3 (range kh*128 .. +128)
    const int gr = lane >> 2;        // fragment group (gid)
    const int gc = lane & 3;         // thread-in-group (tig)

    const float* __restrict__ Uw = d ? U_bw : U_fw;
    const float* __restrict__ br = d ? b_rec_bw : b_rec_fw;

    // stage U packed once (reused all 512 steps)
    for (int idx = tid; idx < 24 * 512; idx += 256) {
        int c = idx >> 9;            // col 0..23 (c = g*8 + ul)
        int k = idx & 511;
        int g = c >> 3;
        float v = Uw[(size_t)k * U3 + g * 512 + u0 + (c & 7)];
        UsW[c * PADW + k] = split_pack(v);
    }

    // epilogue mapping (all 256 threads): batch eb, unit eu
    const int eb = tid >> 3, eu = tid & 7;
    const float brz = br[0*512 + u0 + eu];
    const float brr = br[1*512 + u0 + eu];
    const float brh = br[2*512 + u0 + eu];

    const float* gx = &g_xproj[0][0][0][0];

    const int baseA = (mi*16 + gr) * PADW + 2*gc;   // A word base (row gid)
    const int r0  = mi*16 + gr;
    const int r1  = r0 + 8;
    const int kbase = kh * 128;

    __syncthreads();

    for (int ts = 0; ts < TT; ts++) {
        const int t   = d ? (TT - 1 - ts) : ts;
        const int buf = ts & 1;

        // stage packed h_prev into padded SMEM rows (16 uint4 per thread)
        const uint4* hp_g = (const uint4*)&g_h[d][buf][0][0];
#pragma unroll
        for (int i = 0; i < 16; i++) {
            int id  = tid + i * 256;       // 0..4095 uint4 slots
            int row = id >> 7;
            int q   = id & 127;
            *(uint4*)&hsW[row * PADW + q * 4] = hp_g[id];
        }
        // prefetch epilogue inputs (latency hidden under sync + dot)
        size_t xb = ((size_t)d * (BB*TT) + (size_t)eb * TT + t) * U3;
        float xz = gx[xb + u0 + eu];
        float xr = gx[xb + 512 + u0 + eu];
        float xh = gx[xb + 1024 + u0 + eu];
        int   mt = (tokens[eb * TT + t] != 0);
        __syncthreads();

        // ---- bf16x3 tensor dot: 8 k16-tiles, 3 n-tiles, 9 independent accs
        float Dhh[3][4], Dhl[3][4], Dlh[3][4];
#pragma unroll
        for (int j = 0; j < 3; j++)
#pragma unroll
            for (int q = 0; q < 4; q++) { Dhh[j][q] = 0.f; Dhl[j][q] = 0.f; Dlh[j][q] = 0.f; }

#pragma unroll 2
        for (int kt = 0; kt < 8; kt++) {
            int k0 = kbase + kt * 16;
            uint2 wa0 = *(const uint2*)&hsW[baseA + k0];            // row gid,  k 2gc..+1
            uint2 wa1 = *(const uint2*)&hsW[baseA + 8*PADW + k0];   // row gid+8
            uint2 wa2 = *(const uint2*)&hsW[baseA + k0 + 8];        // k+8
            uint2 wa3 = *(const uint2*)&hsW[baseA + 8*PADW + k0 + 8];
            unsigned ah0 = prmt(wa0.x, wa0.y, 0x5410), al0 = prmt(wa0.x, wa0.y, 0x7632);
            unsigned ah1 = prmt(wa1.x, wa1.y, 0x5410), al1 = prmt(wa1.x, wa1.y, 0x7632);
            unsigned ah2 = prmt(wa2.x, wa2.y, 0x5410), al2 = prmt(wa2.x, wa2.y, 0x7632);
            unsigned ah3 = prmt(wa3.x, wa3.y, 0x5410), al3 = prmt(wa3.x, wa3.y, 0x7632);
#pragma unroll
            for (int j = 0; j < 3; j++) {
                int ub = (j*8 + gr) * PADW + 2*gc + k0;
                uint2 wb0 = *(const uint2*)&UsW[ub];       // k 2gc..+1, col gid
                uint2 wb1 = *(const uint2*)&UsW[ub + 8];   // k+8
                unsigned bh0 = prmt(wb0.x, wb0.y, 0x5410), bl0 = prmt(wb0.x, wb0.y, 0x7632);
                unsigned bh1 = prmt(wb1.x, wb1.y, 0x5410), bl1 = prmt(wb1.x, wb1.y, 0x7632);
                mma_bf16(Dhh[j], ah0, ah1, ah2, ah3, bh0, bh1);
                mma_bf16(Dhl[j], ah0, ah1, ah2, ah3, bl0, bl1);
                mma_bf16(Dlh[j], al0, al1, al2, al3, bh0, bh1);
            }
        }

        // combine split products
        float D[3][4];
#pragma unroll
        for (int j = 0; j < 3; j++)
#pragma unroll
            for (int q = 0; q < 4; q++)
                D[j][q] = Dhh[j][q] + Dhl[j][q] + Dlh[j][q];

        // ---- two-phase k-split reduction through psum (R5 verbatim) ----
        if (kh > 0) {
#pragma unroll
            for (int j = 0; j < 3; j++) {
                int cc = j*8 + gc*2;
                *(float2*)&psum[((kh-1)*32 + r0)*24 + cc] = make_float2(D[j][0], D[j][1]);
                *(float2*)&psum[((kh-1)*32 + r1)*24 + cc] = make_float2(D[j][2], D[j][3]);
            }
        }
        __syncthreads();
        if (kh == 0) {
#pragma unroll
            for (int s = 0; s < 3; s++)
#pragma unroll
                for (int j = 0; j < 3; j++) {
                    int cc = j*8 + gc*2;
                    float2 p0 = *(const float2*)&psum[(s*32 + r0)*24 + cc];
                    float2 p1 = *(const float2*)&psum[(s*32 + r1)*24 + cc];
                    D[j][0] += p0.x; D[j][1] += p0.y;
                    D[j][2] += p1.x; D[j][3] += p1.y;
                }
#pragma unroll
            for (int j = 0; j < 3; j++) {
                int cc = j*8 + gc*2;
                *(float2*)&psum[r0*24 + cc] = make_float2(D[j][0], D[j][1]);
                *(float2*)&psum[r1*24 + cc] = make_float2(D[j][2], D[j][3]);
            }
        }
        __syncthreads();

        // ---- epilogue: all 256 threads, each = one (batch, unit) ----
        {
            float hz = psum[eb*24 + 0  + eu] + brz;
            float hr = psum[eb*24 + 8  + eu] + brr;
            float hh = psum[eb*24 + 16 + eu] + brh;

            float z    = 1.f / (1.f + expf(-(xz + hz)));
            float r    = 1.f / (1.f + expf(-(xr + hr)));
            float cand = tanhf(xh + r * hh);
            float hp   = unsplit(hsW[eb * PADW + u0 + eu]);
            float hn   = z * hp + (1.f - z) * cand;
            if (!mt) hn = hp;

            g_h[d][buf ^ 1][eb][u0 + eu] = split_pack(hn);
            out[((size_t)eb * TT + t) * (2*UU) + (size_t)d * UU + u0 + eu] = hn;
        }

        // ---- inter-block barrier (R5 verbatim) ----
        if (ts + 1 < TT) {
            __syncthreads();
            if (tid == 0) {
                __threadfence();
                atomicAdd(&g_cnt[d][ts], 1u);
                volatile unsigned* c = &g_cnt[d][ts];
                while (*c < NBLK) { }
                __threadfence();
            }
            __syncthreads();
        }
    }
}

// ---------------- launch ----------------------------------------------------
extern "C" void kernel_launch(void* const* d_in, const int* in_sizes, int n_in,
                              void* d_out, int out_size)
{
    const int*   tokens   = (const int*)  d_in[0];
    const float* emb      = (const float*)d_in[1];
    const float* W_fw     = (const float*)d_in[2];
    const float* U_fw     = (const float*)d_in[3];
    const float* b_in_fw  = (const float*)d_in[4];
    const float* b_rec_fw = (const float*)d_in[5];
    const float* W_bw     = (const float*)d_in[6];
    const float* U_bw     = (const float*)d_in[7];
    const float* b_in_bw  = (const float*)d_in[8];
    const float* b_rec_bw = (const float*)d_in[9];
    float* out = (float*)d_out;

    void* p;
    cudaGetSymbolAddress(&p, g_h);
    cudaMemsetAsync(p, 0, sizeof(g_h));
    cudaGetSymbolAddress(&p, g_cnt);
    cudaMemsetAsync(p, 0, sizeof(g_cnt));

    dim3 gA(U3 / BN, (BB * TT) / BM, 2);
    xproj_kernel<<<gA, 256>>>(tokens, emb, W_fw, b_in_fw, W_bw, b_in_bw);

    cudaFuncSetAttribute(gru_kernel,
                         cudaFuncAttributeMaxDynamicSharedMemorySize, SMEM_BYTES);
    gru_kernel<<<RGRID, 256, SMEM_BYTES>>>(tokens, U_fw, b_rec_fw,
                                           U_bw, b_rec_bw, out);
}

// round 10
// speedup vs baseline: 1.8201x; 1.0190x over previous
#include <cuda_runtime.h>
#include <cuda_bf16.h>
#include <math.h>
#include <stdint.h>

#define BB 32
#define TT 512
#define EE 256
#define UU 512
#define U3 1536
#define NBLK 64          // blocks per direction in recurrence
#define RGRID (2*NBLK)   // total recurrence blocks
#define HSTR 520         // gru SMEM ushort stride (260 words -> conflict-free)
#define ASTR 40          // xproj SMEM ushort stride (20 words -> conflict-free)

// ---------------- device scratch (static; no runtime allocation) ------------
__device__ float          g_xproj[2][BB][TT][U3];  // x@W + b_in per direction
__device__ unsigned short g_hh[2][2][BB][UU];      // h hi bf16, double-buffered
__device__ unsigned short g_hl[2][2][BB][UU];      // h lo bf16
__device__ unsigned       g_cnt[2][TT];            // barrier counters (memset 0)

// ---------------- bf16 split helpers ----------------------------------------
__device__ __forceinline__ unsigned short bf16_hi(float v) {
    return __bfloat16_as_ushort(__float2bfloat16_rn(v));
}
__device__ __forceinline__ void split2(float v, unsigned short& h, unsigned short& l) {
    h = bf16_hi(v);
    float fh = __uint_as_float((unsigned)h << 16);
    l = bf16_hi(v - fh);
}
__device__ __forceinline__ float joinhl(unsigned short h, unsigned short l) {
    return __uint_as_float((unsigned)h << 16) + __uint_as_float((unsigned)l << 16);
}

// ---------------- bf16 mma helper (m16n8k16) ---------------------------------
__device__ __forceinline__ void mma_bf16(float* D,
                                         unsigned a0, unsigned a1, unsigned a2, unsigned a3,
                                         unsigned b0, unsigned b1) {
    asm volatile(
        "mma.sync.aligned.m16n8k16.row.col.f32.bf16.bf16.f32 "
        "{%0,%1,%2,%3}, {%4,%5,%6,%7}, {%8,%9}, {%0,%1,%2,%3};"
        : "+f"(D[0]), "+f"(D[1]), "+f"(D[2]), "+f"(D[3])
        : "r"(a0), "r"(a1), "r"(a2), "r"(a3), "r"(b0), "r"(b1));
}

// ---------------- Kernel A: x_proj = emb[tokens] @ W + b_in (bf16x3 MMA) ----
// block: 256 thr = 8 warps; tile BM=128 (8 m-tiles), BN=64, BK=32.
// A = gathered emb rows, B = W; both split hi/lo ushort in SMEM per k-tile.
__global__ void __launch_bounds__(256) xproj_kernel(
    const int* __restrict__ tokens,
    const float* __restrict__ emb,
    const float* __restrict__ W_fw, const float* __restrict__ b_in_fw,
    const float* __restrict__ W_bw, const float* __restrict__ b_in_bw)
{
    __shared__ __align__(16) unsigned short SAh[128 * ASTR];
    __shared__ __align__(16) unsigned short SAl[128 * ASTR];
    __shared__ __align__(16) unsigned short SBh[64 * ASTR];
    __shared__ __align__(16) unsigned short SBl[64 * ASTR];
    __shared__ int toks[128];

    const int d  = blockIdx.z;
    const float* __restrict__ Wp = d ? W_bw : W_fw;
    const float* __restrict__ bp = d ? b_in_bw : b_in_fw;
    const int n0 = blockIdx.x * 64;
    const int m0 = blockIdx.y * 128;
    const int tid = threadIdx.x;
    const int wid = tid >> 5;
    const int lane = tid & 31;
    const int gr = lane >> 2;
    const int gc = lane & 3;

    if (tid < 128) toks[tid] = tokens[m0 + tid];
    __syncthreads();

    const unsigned* SAhw = (const unsigned*)SAh;
    const unsigned* SAlw = (const unsigned*)SAl;
    const unsigned* SBhw = (const unsigned*)SBh;
    const unsigned* SBlw = (const unsigned*)SBl;

    float D[8][4];
#pragma unroll
    for (int j = 0; j < 8; j++)
#pragma unroll
        for (int q = 0; q < 4; q++) D[j][q] = 0.f;

    const int arow = tid >> 1;             // A-stage row
    const int ak   = (tid & 1) * 16;       // A-stage k-half
    const int bk   = tid >> 3;             // B-stage k (0..31)
    const int bn   = (tid & 7) * 8;        // B-stage n-chunk

    const int baseA0 = (wid * 16 + gr) * (ASTR/2);
    const int baseA1 = baseA0 + 8 * (ASTR/2);

    for (int k0 = 0; k0 < EE; k0 += 32) {
        // stage A: 16 consecutive k's per thread, split hi/lo
        {
            const float* src = emb + (size_t)toks[arow] * EE + k0 + ak;
            float4 v0 = *(const float4*)(src);
            float4 v1 = *(const float4*)(src + 4);
            float4 v2 = *(const float4*)(src + 8);
            float4 v3 = *(const float4*)(src + 12);
            float vv[16] = {v0.x,v0.y,v0.z,v0.w, v1.x,v1.y,v1.z,v1.w,
                            v2.x,v2.y,v2.z,v2.w, v3.x,v3.y,v3.z,v3.w};
            unsigned short* ph = SAh + arow * ASTR + ak;
            unsigned short* pl = SAl + arow * ASTR + ak;
#pragma unroll
            for (int i = 0; i < 16; i++) {
                unsigned short h, l;
                split2(vv[i], h, l);
                ph[i] = h; pl[i] = l;
            }
        }
        // stage B: 8 consecutive n's per thread at one k, split hi/lo (transpose)
        {
            const float* src = Wp + (size_t)(k0 + bk) * U3 + n0 + bn;
            float4 v0 = *(const float4*)(src);
            float4 v1 = *(const float4*)(src + 4);
            float vv[8] = {v0.x,v0.y,v0.z,v0.w, v1.x,v1.y,v1.z,v1.w};
#pragma unroll
            for (int c = 0; c < 8; c++) {
                unsigned short h, l;
                split2(vv[c], h, l);
                SBh[(bn + c) * ASTR + bk] = h;
                SBl[(bn + c) * ASTR + bk] = l;
            }
        }
        __syncthreads();

#pragma unroll
        for (int kt = 0; kt < 2; kt++) {
            int kw = kt * 8;
            unsigned ah0 = SAhw[baseA0 + kw + gc];
            unsigned ah1 = SAhw[baseA1 + kw + gc];
            unsigned ah2 = SAhw[baseA0 + kw + gc + 4];
            unsigned ah3 = SAhw[baseA1 + kw + gc + 4];
            unsigned al0 = SAlw[baseA0 + kw + gc];
            unsigned al1 = SAlw[baseA1 + kw + gc];
            unsigned al2 = SAlw[baseA0 + kw + gc + 4];
            unsigned al3 = SAlw[baseA1 + kw + gc + 4];
#pragma unroll
            for (int j = 0; j < 8; j++) {
                int ub = (j * 8 + gr) * (ASTR/2) + kw + gc;
                unsigned bh0 = SBhw[ub], bh1 = SBhw[ub + 4];
                unsigned bl0 = SBlw[ub], bl1 = SBlw[ub + 4];
                mma_bf16(D[j], ah0, ah1, ah2, ah3, bh0, bh1);
                mma_bf16(D[j], ah0, ah1, ah2, ah3, bl0, bl1);
                mma_bf16(D[j], al0, al1, al2, al3, bh0, bh1);
            }
        }
        __syncthreads();
    }

    // epilogue: add bias, store fp32 rows
    float* gx = &g_xproj[0][0][0][0];
    const size_t mbase = (size_t)d * (BB*TT) + m0 + wid * 16;
#pragma unroll
    for (int j = 0; j < 8; j++) {
        int cc = n0 + j * 8 + gc * 2;
        float2 bias = *(const float2*)(bp + cc);
        float2 vlo = { D[j][0] + bias.x, D[j][1] + bias.y };
        float2 vhi = { D[j][2] + bias.x, D[j][3] + bias.y };
        *(float2*)(gx + (mbase + gr)     * U3 + cc) = vlo;
        *(float2*)(gx + (mbase + gr + 8) * U3 + cc) = vhi;
    }
}

// ---------------- Kernel B: persistent GRU recurrence (bf16x3, no PRMT) -----
// R5/R9 skeleton: 128 blocks (64/dir), 256 threads = 8 warps (2 m x 4 ksplit),
// two-phase psum, single-counter barrier. h and U stored as SEPARATE hi/lo
// ushort arrays -> mma operand words load directly (no PRMT).
#define SMEM_BYTES ((32*HSTR*2 + 24*HSTR*2) * 2 + 3*32*24*4 + 64)

__global__ void __launch_bounds__(256, 1) gru_kernel(
    const int* __restrict__ tokens,
    const float* __restrict__ U_fw, const float* __restrict__ b_rec_fw,
    const float* __restrict__ U_bw, const float* __restrict__ b_rec_bw,
    float* __restrict__ out)
{
    extern __shared__ unsigned short smemus[];
    unsigned short* hsH = smemus;               // [32][520]
    unsigned short* hsL = hsH + 32*HSTR;        // [32][520]
    unsigned short* UsH = hsL + 32*HSTR;        // [24][520]
    unsigned short* UsL = UsH + 24*HSTR;        // [24][520]
    float* psum = (float*)(UsL + 24*HSTR);      // [3][32][24]

    const unsigned* hsHw = (const unsigned*)hsH;
    const unsigned* hsLw = (const unsigned*)hsL;
    const unsigned* UsHw = (const unsigned*)UsH;
    const unsigned* UsLw = (const unsigned*)UsL;

    const int bid = blockIdx.x;
    const int d   = bid >> 6;
    const int jb  = bid & (NBLK - 1);
    const int u0  = jb * 8;
    const int tid = threadIdx.x;
    const int wid = tid >> 5;
    const int lane = tid & 31;
    const int mi = wid & 1;          // m-tile (rows mi*16 .. +15)
    const int kh = wid >> 1;         // k-split 0..3 (range kh*128 .. +128)
    const int gr = lane >> 2;
    const int gc = lane & 3;

    const float* __restrict__ Uw = d ? U_bw : U_fw;
    const float* __restrict__ br = d ? b_rec_bw : b_rec_fw;

    // stage U hi/lo once (reused all 512 steps)
    for (int idx = tid; idx < 24 * 512; idx += 256) {
        int c = idx >> 9;            // col 0..23 (c = g*8 + ul)
        int k = idx & 511;
        int g = c >> 3;
        float v = Uw[(size_t)k * U3 + g * 512 + u0 + (c & 7)];
        unsigned short h, l;
        split2(v, h, l);
        UsH[c * HSTR + k] = h;
        UsL[c * HSTR + k] = l;
    }

    // epilogue mapping (all 256 threads): batch eb, unit eu
    const int eb = tid >> 3, eu = tid & 7;
    const float brz = br[0*512 + u0 + eu];
    const float brr = br[1*512 + u0 + eu];
    const float brh = br[2*512 + u0 + eu];

    const float* gx = &g_xproj[0][0][0][0];

    const int base0 = (mi*16 + gr) * (HSTR/2);   // word base, A rows gr / gr+8
    const int base1 = base0 + 8 * (HSTR/2);
    const int r0  = mi*16 + gr;
    const int r1  = r0 + 8;
    const int kwbase = kh * 64;                  // word offset of k-range

    __syncthreads();

    for (int ts = 0; ts < TT; ts++) {
        const int t   = d ? (TT - 1 - ts) : ts;
        const int buf = ts & 1;

        // stage packed h_prev hi/lo (8+8 uint4 per thread)
        const uint4* srcH = (const uint4*)&g_hh[d][buf][0][0];
        const uint4* srcL = (const uint4*)&g_hl[d][buf][0][0];
        uint4* dstH = (uint4*)hsH;
        uint4* dstL = (uint4*)hsL;
#pragma unroll
        for (int i = 0; i < 8; i++) {
            int id  = tid + i * 256;       // 0..2047 uint4 slots (32 rows x 64)
            int row = id >> 6;
            int q   = id & 63;
            dstH[row * (HSTR/8) + q] = srcH[id];
            dstL[row * (HSTR/8) + q] = srcL[id];
        }
        // prefetch epilogue inputs
        size_t xb = ((size_t)d * (BB*TT) + (size_t)eb * TT + t) * U3;
        float xz = gx[xb + u0 + eu];
        float xr = gx[xb + 512 + u0 + eu];
        float xh = gx[xb + 1024 + u0 + eu];
        int   mt = (tokens[eb * TT + t] != 0);
        __syncthreads();

        // ---- bf16x3 tensor dot: 8 k16-tiles, 3 n-tiles, 9 independent accs
        float Dhh[3][4], Dhl[3][4], Dlh[3][4];
#pragma unroll
        for (int j = 0; j < 3; j++)
#pragma unroll
            for (int q = 0; q < 4; q++) { Dhh[j][q] = 0.f; Dhl[j][q] = 0.f; Dlh[j][q] = 0.f; }

#pragma unroll 2
        for (int kt = 0; kt < 8; kt++) {
            int kw = kwbase + kt * 8;
            unsigned ah0 = hsHw[base0 + kw + gc];
            unsigned ah1 = hsHw[base1 + kw + gc];
            unsigned ah2 = hsHw[base0 + kw + gc + 4];
            unsigned ah3 = hsHw[base1 + kw + gc + 4];
            unsigned al0 = hsLw[base0 + kw + gc];
            unsigned al1 = hsLw[base1 + kw + gc];
            unsigned al2 = hsLw[base0 + kw + gc + 4];
            unsigned al3 = hsLw[base1 + kw + gc + 4];
#pragma unroll
            for (int j = 0; j < 3; j++) {
                int ub = (j*8 + gr) * (HSTR/2) + kw + gc;
                unsigned bh0 = UsHw[ub], bh1 = UsHw[ub + 4];
                unsigned bl0 = UsLw[ub], bl1 = UsLw[ub + 4];
                mma_bf16(Dhh[j], ah0, ah1, ah2, ah3, bh0, bh1);
                mma_bf16(Dhl[j], ah0, ah1, ah2, ah3, bl0, bl1);
                mma_bf16(Dlh[j], al0, al1, al2, al3, bh0, bh1);
            }
        }

        float D[3][4];
#pragma unroll
        for (int j = 0; j < 3; j++)
#pragma unroll
            for (int q = 0; q < 4; q++)
                D[j][q] = Dhh[j][q] + Dhl[j][q] + Dlh[j][q];

        // ---- two-phase k-split reduction through psum (verified) ----
        if (kh > 0) {
#pragma unroll
            for (int j = 0; j < 3; j++) {
                int cc = j*8 + gc*2;
                *(float2*)&psum[((kh-1)*32 + r0)*24 + cc] = make_float2(D[j][0], D[j][1]);
                *(float2*)&psum[((kh-1)*32 + r1)*24 + cc] = make_float2(D[j][2], D[j][3]);
            }
        }
        __syncthreads();
        if (kh == 0) {
#pragma unroll
            for (int s = 0; s < 3; s++)
#pragma unroll
                for (int j = 0; j < 3; j++) {
                    int cc = j*8 + gc*2;
                    float2 p0 = *(const float2*)&psum[(s*32 + r0)*24 + cc];
                    float2 p1 = *(const float2*)&psum[(s*32 + r1)*24 + cc];
                    D[j][0] += p0.x; D[j][1] += p0.y;
                    D[j][2] += p1.x; D[j][3] += p1.y;
                }
#pragma unroll
            for (int j = 0; j < 3; j++) {
                int cc = j*8 + gc*2;
                *(float2*)&psum[r0*24 + cc] = make_float2(D[j][0], D[j][1]);
                *(float2*)&psum[r1*24 + cc] = make_float2(D[j][2], D[j][3]);
            }
        }
        __syncthreads();

        // ---- epilogue: all 256 threads, each = one (batch, unit) ----
        {
            float hz = psum[eb*24 + 0  + eu] + brz;
            float hr = psum[eb*24 + 8  + eu] + brr;
            float hh = psum[eb*24 + 16 + eu] + brh;

            float z    = 1.f / (1.f + expf(-(xz + hz)));
            float r    = 1.f / (1.f + expf(-(xr + hr)));
            float cand = tanhf(xh + r * hh);
            float hp   = joinhl(hsH[eb * HSTR + u0 + eu], hsL[eb * HSTR + u0 + eu]);
            float hn   = z * hp + (1.f - z) * cand;
            if (!mt) hn = hp;

            unsigned short hnh, hnl;
            split2(hn, hnh, hnl);
            g_hh[d][buf ^ 1][eb][u0 + eu] = hnh;
            g_hl[d][buf ^ 1][eb][u0 + eu] = hnl;
            out[((size_t)eb * TT + t) * (2*UU) + (size_t)d * UU + u0 + eu] = hn;
        }

        // ---- inter-block barrier (verified) ----
        if (ts + 1 < TT) {
            __syncthreads();
            if (tid == 0) {
                __threadfence();
                atomicAdd(&g_cnt[d][ts], 1u);
                volatile unsigned* c = &g_cnt[d][ts];
                while (*c < NBLK) { }
                __threadfence();
            }
            __syncthreads();
        }
    }
}

// ---------------- launch ----------------------------------------------------
extern "C" void kernel_launch(void* const* d_in, const int* in_sizes, int n_in,
                              void* d_out, int out_size)
{
    const int*   tokens   = (const int*)  d_in[0];
    const float* emb      = (const float*)d_in[1];
    const float* W_fw     = (const float*)d_in[2];
    const float* U_fw     = (const float*)d_in[3];
    const float* b_in_fw  = (const float*)d_in[4];
    const float* b_rec_fw = (const float*)d_in[5];
    const float* W_bw     = (const float*)d_in[6];
    const float* U_bw     = (const float*)d_in[7];
    const float* b_in_bw  = (const float*)d_in[8];
    const float* b_rec_bw = (const float*)d_in[9];
    float* out = (float*)d_out;

    void* p;
    cudaGetSymbolAddress(&p, g_hh);
    cudaMemsetAsync(p, 0, sizeof(g_hh));
    cudaGetSymbolAddress(&p, g_hl);
    cudaMemsetAsync(p, 0, sizeof(g_hl));
    cudaGetSymbolAddress(&p, g_cnt);
    cudaMemsetAsync(p, 0, sizeof(g_cnt));

    dim3 gA(U3 / 64, (BB * TT) / 128, 2);
    xproj_kernel<<<gA, 256>>>(tokens, emb, W_fw, b_in_fw, W_bw, b_in_bw);

    cudaFuncSetAttribute(gru_kernel,
                         cudaFuncAttributeMaxDynamicSharedMemorySize, SMEM_BYTES);
    gru_kernel<<<RGRID, 256, SMEM_BYTES>>>(tokens, U_fw, b_rec_fw,
                                           U_bw, b_rec_bw, out);
}

// round 11
// speedup vs baseline: 1.8826x; 1.0343x over previous
#include <cuda_runtime.h>
#include <cuda_bf16.h>
#include <math.h>
#include <stdint.h>

#define BB 32
#define TT 512
#define EE 256
#define UU 512
#define U3 1536
#define NBLK 64          // blocks per direction in recurrence
#define RGRID (2*NBLK)   // total recurrence blocks
#define HSTR 520         // gru SMEM ushort stride (260 words -> conflict-free)
#define ASTR 40          // xproj SMEM ushort stride (20 words -> conflict-free)

// ---------------- device scratch (static; no runtime allocation) ------------
__device__ float          g_xproj[2][BB][TT][U3];  // x@W + b_in per direction
__device__ unsigned short g_hh[2][2][BB][UU];      // h hi bf16, double-buffered
__device__ unsigned short g_hl[2][2][BB][UU];      // h lo bf16
__device__ unsigned       g_cnt[2][TT];            // barrier counters (memset 0)

// ---------------- bf16 split helpers ----------------------------------------
__device__ __forceinline__ unsigned short bf16_hi(float v) {
    return __bfloat16_as_ushort(__float2bfloat16_rn(v));
}
__device__ __forceinline__ void split2(float v, unsigned short& h, unsigned short& l) {
    h = bf16_hi(v);
    float fh = __uint_as_float((unsigned)h << 16);
    l = bf16_hi(v - fh);
}
__device__ __forceinline__ float joinhl(unsigned short h, unsigned short l) {
    return __uint_as_float((unsigned)h << 16) + __uint_as_float((unsigned)l << 16);
}

// ---------------- bf16 mma helper (m16n8k16) ---------------------------------
__device__ __forceinline__ void mma_bf16(float* D,
                                         unsigned a0, unsigned a1, unsigned a2, unsigned a3,
                                         unsigned b0, unsigned b1) {
    asm volatile(
        "mma.sync.aligned.m16n8k16.row.col.f32.bf16.bf16.f32 "
        "{%0,%1,%2,%3}, {%4,%5,%6,%7}, {%8,%9}, {%0,%1,%2,%3};"
        : "+f"(D[0]), "+f"(D[1]), "+f"(D[2]), "+f"(D[3])
        : "r"(a0), "r"(a1), "r"(a2), "r"(a3), "r"(b0), "r"(b1));
}

// ---------------- Kernel A: x_proj = emb[tokens] @ W + b_in (bf16x3 MMA) ----
__global__ void __launch_bounds__(256) xproj_kernel(
    const int* __restrict__ tokens,
    const float* __restrict__ emb,
    const float* __restrict__ W_fw, const float* __restrict__ b_in_fw,
    const float* __restrict__ W_bw, const float* __restrict__ b_in_bw)
{
    __shared__ __align__(16) unsigned short SAh[128 * ASTR];
    __shared__ __align__(16) unsigned short SAl[128 * ASTR];
    __shared__ __align__(16) unsigned short SBh[64 * ASTR];
    __shared__ __align__(16) unsigned short SBl[64 * ASTR];
    __shared__ int toks[128];

    const int d  = blockIdx.z;
    const float* __restrict__ Wp = d ? W_bw : W_fw;
    const float* __restrict__ bp = d ? b_in_bw : b_in_fw;
    const int n0 = blockIdx.x * 64;
    const int m0 = blockIdx.y * 128;
    const int tid = threadIdx.x;
    const int wid = tid >> 5;
    const int lane = tid & 31;
    const int gr = lane >> 2;
    const int gc = lane & 3;

    if (tid < 128) toks[tid] = tokens[m0 + tid];
    __syncthreads();

    const unsigned* SAhw = (const unsigned*)SAh;
    const unsigned* SAlw = (const unsigned*)SAl;
    const unsigned* SBhw = (const unsigned*)SBh;
    const unsigned* SBlw = (const unsigned*)SBl;

    float D[8][4];
#pragma unroll
    for (int j = 0; j < 8; j++)
#pragma unroll
        for (int q = 0; q < 4; q++) D[j][q] = 0.f;

    const int arow = tid >> 1;
    const int ak   = (tid & 1) * 16;
    const int bk   = tid >> 3;
    const int bn   = (tid & 7) * 8;

    const int baseA0 = (wid * 16 + gr) * (ASTR/2);
    const int baseA1 = baseA0 + 8 * (ASTR/2);

    for (int k0 = 0; k0 < EE; k0 += 32) {
        {
            const float* src = emb + (size_t)toks[arow] * EE + k0 + ak;
            float4 v0 = *(const float4*)(src);
            float4 v1 = *(const float4*)(src + 4);
            float4 v2 = *(const float4*)(src + 8);
            float4 v3 = *(const float4*)(src + 12);
            float vv[16] = {v0.x,v0.y,v0.z,v0.w, v1.x,v1.y,v1.z,v1.w,
                            v2.x,v2.y,v2.z,v2.w, v3.x,v3.y,v3.z,v3.w};
            unsigned short* ph = SAh + arow * ASTR + ak;
            unsigned short* pl = SAl + arow * ASTR + ak;
#pragma unroll
            for (int i = 0; i < 16; i++) {
                unsigned short h, l;
                split2(vv[i], h, l);
                ph[i] = h; pl[i] = l;
            }
        }
        {
            const float* src = Wp + (size_t)(k0 + bk) * U3 + n0 + bn;
            float4 v0 = *(const float4*)(src);
            float4 v1 = *(const float4*)(src + 4);
            float vv[8] = {v0.x,v0.y,v0.z,v0.w, v1.x,v1.y,v1.z,v1.w};
#pragma unroll
            for (int c = 0; c < 8; c++) {
                unsigned short h, l;
                split2(vv[c], h, l);
                SBh[(bn + c) * ASTR + bk] = h;
                SBl[(bn + c) * ASTR + bk] = l;
            }
        }
        __syncthreads();

#pragma unroll
        for (int kt = 0; kt < 2; kt++) {
            int kw = kt * 8;
            unsigned ah0 = SAhw[baseA0 + kw + gc];
            unsigned ah1 = SAhw[baseA1 + kw + gc];
            unsigned ah2 = SAhw[baseA0 + kw + gc + 4];
            unsigned ah3 = SAhw[baseA1 + kw + gc + 4];
            unsigned al0 = SAlw[baseA0 + kw + gc];
            unsigned al1 = SAlw[baseA1 + kw + gc];
            unsigned al2 = SAlw[baseA0 + kw + gc + 4];
            unsigned al3 = SAlw[baseA1 + kw + gc + 4];
#pragma unroll
            for (int j = 0; j < 8; j++) {
                int ub = (j * 8 + gr) * (ASTR/2) + kw + gc;
                unsigned bh0 = SBhw[ub], bh1 = SBhw[ub + 4];
                unsigned bl0 = SBlw[ub], bl1 = SBlw[ub + 4];
                mma_bf16(D[j], ah0, ah1, ah2, ah3, bh0, bh1);
                mma_bf16(D[j], ah0, ah1, ah2, ah3, bl0, bl1);
                mma_bf16(D[j], al0, al1, al2, al3, bh0, bh1);
            }
        }
        __syncthreads();
    }

    float* gx = &g_xproj[0][0][0][0];
    const size_t mbase = (size_t)d * (BB*TT) + m0 + wid * 16;
#pragma unroll
    for (int j = 0; j < 8; j++) {
        int cc = n0 + j * 8 + gc * 2;
        float2 bias = *(const float2*)(bp + cc);
        float2 vlo = { D[j][0] + bias.x, D[j][1] + bias.y };
        float2 vhi = { D[j][2] + bias.x, D[j][3] + bias.y };
        *(float2*)(gx + (mbase + gr)     * U3 + cc) = vlo;
        *(float2*)(gx + (mbase + gr + 8) * U3 + cc) = vhi;
    }
}

// ---------------- Kernel B: persistent GRU recurrence (bf16x3, warp-local) --
// R10 skeleton: 128 blocks (64/dir), 256 threads = 8 warps (2 m x 4 ksplit),
// two-phase psum, single-counter barrier. NEW: each warp stages only its own
// 16-row x 128-k hi/lo block via __ldcg (+ __syncwarp, no block sync before
// the dot); fast-math epilogue.
#define SMEM_BYTES ((32*HSTR*2 + 24*HSTR*2) * 2 + 3*32*24*4 + 64)

__global__ void __launch_bounds__(256, 1) gru_kernel(
    const int* __restrict__ tokens,
    const float* __restrict__ U_fw, const float* __restrict__ b_rec_fw,
    const float* __restrict__ U_bw, const float* __restrict__ b_rec_bw,
    float* __restrict__ out)
{
    extern __shared__ unsigned short smemus[];
    unsigned short* hsH = smemus;               // [32][520]
    unsigned short* hsL = hsH + 32*HSTR;        // [32][520]
    unsigned short* UsH = hsL + 32*HSTR;        // [24][520]
    unsigned short* UsL = UsH + 24*HSTR;        // [24][520]
    float* psum = (float*)(UsL + 24*HSTR);      // [3][32][24]

    const unsigned* hsHw = (const unsigned*)hsH;
    const unsigned* hsLw = (const unsigned*)hsL;
    const unsigned* UsHw = (const unsigned*)UsH;
    const unsigned* UsLw = (const unsigned*)UsL;

    const int bid = blockIdx.x;
    const int d   = bid >> 6;
    const int jb  = bid & (NBLK - 1);
    const int u0  = jb * 8;
    const int tid = threadIdx.x;
    const int wid = tid >> 5;
    const int lane = tid & 31;
    const int mi = wid & 1;          // m-tile (rows mi*16 .. +15)
    const int kh = wid >> 1;         // k-split 0..3 (range kh*128 .. +128)
    const int gr = lane >> 2;
    const int gc = lane & 3;

    const float* __restrict__ Uw = d ? U_bw : U_fw;
    const float* __restrict__ br = d ? b_rec_bw : b_rec_fw;

    // stage U hi/lo once (reused all 512 steps)
    for (int idx = tid; idx < 24 * 512; idx += 256) {
        int c = idx >> 9;            // col 0..23 (c = g*8 + ul)
        int k = idx & 511;
        int g = c >> 3;
        float v = Uw[(size_t)k * U3 + g * 512 + u0 + (c & 7)];
        unsigned short h, l;
        split2(v, h, l);
        UsH[c * HSTR + k] = h;
        UsL[c * HSTR + k] = l;
    }

    // epilogue mapping (all 256 threads): batch eb, unit eu
    const int eb = tid >> 3, eu = tid & 7;
    const float brz = br[0*512 + u0 + eu];
    const float brr = br[1*512 + u0 + eu];
    const float brh = br[2*512 + u0 + eu];

    const float* gx = &g_xproj[0][0][0][0];

    const int base0 = (mi*16 + gr) * (HSTR/2);   // word base, A rows gr / gr+8
    const int base1 = base0 + 8 * (HSTR/2);
    const int r0  = mi*16 + gr;
    const int r1  = r0 + 8;
    const int kwbase = kh * 64;                  // word offset of k-range
    const int srow = mi * 16;                    // staging row base
    const int sk   = kh * 128;                   // staging k base (ushorts)

    __syncthreads();

    for (int ts = 0; ts < TT; ts++) {
        const int t   = d ? (TT - 1 - ts) : ts;
        const int buf = ts & 1;

        // prefetch epilogue inputs early (DRAM latency hidden under dot)
        size_t xb = ((size_t)d * (BB*TT) + (size_t)eb * TT + t) * U3;
        float xz = gx[xb + u0 + eu];
        float xr = gx[xb + 512 + u0 + eu];
        float xh = gx[xb + 1024 + u0 + eu];
        int   mt = (tokens[eb * TT + t] != 0);

        // warp-local h staging: rows [srow, srow+16), k [sk, sk+128) hi+lo
#pragma unroll
        for (int i = 0; i < 8; i++) {
            int uid = lane + 32 * i;           // 0..255
            int row = srow + (uid >> 4);
            int col = uid & 15;                // uint4 slot within 128-ushort chunk
            uint4 vH = __ldcg((const uint4*)&g_hh[d][buf][row][sk] + col);
            uint4 vL = __ldcg((const uint4*)&g_hl[d][buf][row][sk] + col);
            *(uint4*)&hsH[row * HSTR + sk + col * 8] = vH;
            *(uint4*)&hsL[row * HSTR + sk + col * 8] = vL;
        }
        __syncwarp();

        // ---- bf16x3 tensor dot: 8 k16-tiles, 3 n-tiles, 9 independent accs
        float Dhh[3][4], Dhl[3][4], Dlh[3][4];
#pragma unroll
        for (int j = 0; j < 3; j++)
#pragma unroll
            for (int q = 0; q < 4; q++) { Dhh[j][q] = 0.f; Dhl[j][q] = 0.f; Dlh[j][q] = 0.f; }

#pragma unroll 2
        for (int kt = 0; kt < 8; kt++) {
            int kw = kwbase + kt * 8;
            unsigned ah0 = hsHw[base0 + kw + gc];
            unsigned ah1 = hsHw[base1 + kw + gc];
            unsigned ah2 = hsHw[base0 + kw + gc + 4];
            unsigned ah3 = hsHw[base1 + kw + gc + 4];
            unsigned al0 = hsLw[base0 + kw + gc];
            unsigned al1 = hsLw[base1 + kw + gc];
            unsigned al2 = hsLw[base0 + kw + gc + 4];
            unsigned al3 = hsLw[base1 + kw + gc + 4];
#pragma unroll
            for (int j = 0; j < 3; j++) {
                int ub = (j*8 + gr) * (HSTR/2) + kw + gc;
                unsigned bh0 = UsHw[ub], bh1 = UsHw[ub + 4];
                unsigned bl0 = UsLw[ub], bl1 = UsLw[ub + 4];
                mma_bf16(Dhh[j], ah0, ah1, ah2, ah3, bh0, bh1);
                mma_bf16(Dhl[j], ah0, ah1, ah2, ah3, bl0, bl1);
                mma_bf16(Dlh[j], al0, al1, al2, al3, bh0, bh1);
            }
        }

        float D[3][4];
#pragma unroll
        for (int j = 0; j < 3; j++)
#pragma unroll
            for (int q = 0; q < 4; q++)
                D[j][q] = Dhh[j][q] + Dhl[j][q] + Dlh[j][q];

        // ---- two-phase k-split reduction through psum (verified) ----
        if (kh > 0) {
#pragma unroll
            for (int j = 0; j < 3; j++) {
                int cc = j*8 + gc*2;
                *(float2*)&psum[((kh-1)*32 + r0)*24 + cc] = make_float2(D[j][0], D[j][1]);
                *(float2*)&psum[((kh-1)*32 + r1)*24 + cc] = make_float2(D[j][2], D[j][3]);
            }
        }
        __syncthreads();
        if (kh == 0) {
#pragma unroll
            for (int s = 0; s < 3; s++)
#pragma unroll
                for (int j = 0; j < 3; j++) {
                    int cc = j*8 + gc*2;
                    float2 p0 = *(const float2*)&psum[(s*32 + r0)*24 + cc];
                    float2 p1 = *(const float2*)&psum[(s*32 + r1)*24 + cc];
                    D[j][0] += p0.x; D[j][1] += p0.y;
                    D[j][2] += p1.x; D[j][3] += p1.y;
                }
#pragma unroll
            for (int j = 0; j < 3; j++) {
                int cc = j*8 + gc*2;
                *(float2*)&psum[r0*24 + cc] = make_float2(D[j][0], D[j][1]);
                *(float2*)&psum[r1*24 + cc] = make_float2(D[j][2], D[j][3]);
            }
        }
        __syncthreads();

        // ---- epilogue: all 256 threads, each = one (batch, unit) ----
        {
            float hz = psum[eb*24 + 0  + eu] + brz;
            float hr = psum[eb*24 + 8  + eu] + brr;
            float hh = psum[eb*24 + 16 + eu] + brh;

            float z    = __fdividef(1.f, 1.f + __expf(-(xz + hz)));
            float r    = __fdividef(1.f, 1.f + __expf(-(xr + hr)));
            float ta   = xh + r * hh;
            float cand = 1.f - __fdividef(2.f, __expf(2.f * ta) + 1.f);
            float hp   = joinhl(hsH[eb * HSTR + u0 + eu], hsL[eb * HSTR + u0 + eu]);
            float hn   = z * hp + (1.f - z) * cand;
            if (!mt) hn = hp;

            unsigned short hnh, hnl;
            split2(hn, hnh, hnl);
            g_hh[d][buf ^ 1][eb][u0 + eu] = hnh;
            g_hl[d][buf ^ 1][eb][u0 + eu] = hnl;
            out[((size_t)eb * TT + t) * (2*UU) + (size_t)d * UU + u0 + eu] = hn;
        }

        // ---- inter-block barrier (verified) ----
        if (ts + 1 < TT) {
            __syncthreads();
            if (tid == 0) {
                __threadfence();
                atomicAdd(&g_cnt[d][ts], 1u);
                volatile unsigned* c = &g_cnt[d][ts];
                while (*c < NBLK) { }
                __threadfence();
            }
            __syncthreads();
        }
    }
}

// ---------------- launch ----------------------------------------------------
extern "C" void kernel_launch(void* const* d_in, const int* in_sizes, int n_in,
                              void* d_out, int out_size)
{
    const int*   tokens   = (const int*)  d_in[0];
    const float* emb      = (const float*)d_in[1];
    const float* W_fw     = (const float*)d_in[2];
    const float* U_fw     = (const float*)d_in[3];
    const float* b_in_fw  = (const float*)d_in[4];
    const float* b_rec_fw = (const float*)d_in[5];
    const float* W_bw     = (const float*)d_in[6];
    const float* U_bw     = (const float*)d_in[7];
    const float* b_in_bw  = (const float*)d_in[8];
    const float* b_rec_bw = (const float*)d_in[9];
    float* out = (float*)d_out;

    void* p;
    cudaGetSymbolAddress(&p, g_hh);
    cudaMemsetAsync(p, 0, sizeof(g_hh));
    cudaGetSymbolAddress(&p, g_hl);
    cudaMemsetAsync(p, 0, sizeof(g_hl));
    cudaGetSymbolAddress(&p, g_cnt);
    cudaMemsetAsync(p, 0, sizeof(g_cnt));

    dim3 gA(U3 / 64, (BB * TT) / 128, 2);
    xproj_kernel<<<gA, 256>>>(tokens, emb, W_fw, b_in_fw, W_bw, b_in_bw);

    cudaFuncSetAttribute(gru_kernel,
                         cudaFuncAttributeMaxDynamicSharedMemorySize, SMEM_BYTES);
    gru_kernel<<<RGRID, 256, SMEM_BYTES>>>(tokens, U_fw, b_rec_fw,
                                           U_bw, b_rec_bw, out);
}